// round 3
// baseline (speedup 1.0000x reference)
#include <cuda_runtime.h>
#include <math.h>

#define Bb 16
#define Qd 2048
#define Kd 2048
#define Fd 128
#define QT 64
#define KT 64
#define NT 256
#define LSTR 132   // padded row stride (floats) for Q/K/V tiles
#define SSTR 65    // padded row stride for S/D tiles

#define SMEM_FLOATS (3*QT*LSTR + 2*QT*SSTR + QT*2 + KT*2 + 3*QT)
#define SMEM_BYTES (SMEM_FLOATS * 4)

extern __shared__ float sm[];

__global__ void __launch_bounds__(NT, 1) alibi_attn_kernel(
    const float* __restrict__ q, const float* __restrict__ k, const float* __restrict__ v,
    const float* __restrict__ cq, const float* __restrict__ ck,
    const int* __restrict__ am, const int* __restrict__ alm,
    const float* __restrict__ bias_scale, const float* __restrict__ running_mean,
    float* __restrict__ out)
{
    const int b  = blockIdx.y;
    const int q0 = blockIdx.x * QT;
    const int tid = threadIdx.x;

    float* Qs = sm;
    float* Ks = Qs + QT*LSTR;
    float* Vs = Ks + KT*LSTR;
    float* SE = Vs + KT*LSTR;
    float* DD = SE + QT*SSTR;
    float* CQ = DD + QT*SSTR;
    float* CK = CQ + QT*2;
    float* MR = CK + KT*2;
    float* LR = MR + QT;
    float* RS = LR + QT;

    const float dscale = bias_scale[0] / running_mean[0];
    const float sscale = rsqrtf((float)Fd);

    // ---- load Q tile (once) ----
    {
        const float* qbase = q + ((size_t)b*Qd + q0)*Fd;
        #pragma unroll
        for (int it = 0; it < (QT*Fd/4)/NT; it++) {
            int i = tid + it*NT;
            int row = i >> 5;       // Fd/4 = 32 float4 per row
            int c4  = i & 31;
            float4 t = *(const float4*)(qbase + row*Fd + c4*4);
            *(float4*)(Qs + row*LSTR + c4*4) = t;
        }
        if (tid < QT) {
            CQ[tid*2+0] = cq[((size_t)b*Qd + q0 + tid)*2 + 0];
            CQ[tid*2+1] = cq[((size_t)b*Qd + q0 + tid)*2 + 1];
            MR[tid] = -INFINITY;
            LR[tid] = 0.f;
        }
    }

    // phase-B output mapping: 8 q-rows x 4 f-cols per thread
    const int bq0 = (tid >> 5) * 8;
    const int bf0 = (tid & 31) * 4;
    float acc1[8][4], acc2[8][4];
    #pragma unroll
    for (int i = 0; i < 8; i++)
        #pragma unroll
        for (int c = 0; c < 4; c++) { acc1[i][c] = 0.f; acc2[i][c] = 0.f; }

    // phase-A S mapping: 4x4 micro-tile per thread
    const int aq0 = (tid >> 4) * 4;
    const int ak0 = (tid & 15) * 4;

    __syncthreads();

    for (int k0 = 0; k0 < Kd; k0 += KT) {
        // ---- load K/V tiles ----
        {
            const float* kbase = k + ((size_t)b*Kd + k0)*Fd;
            const float* vbase = v + ((size_t)b*Kd + k0)*Fd;
            #pragma unroll
            for (int it = 0; it < (KT*Fd/4)/NT; it++) {
                int i = tid + it*NT;
                int row = i >> 5;
                int c4  = i & 31;
                *(float4*)(Ks + row*LSTR + c4*4) = *(const float4*)(kbase + row*Fd + c4*4);
                *(float4*)(Vs + row*LSTR + c4*4) = *(const float4*)(vbase + row*Fd + c4*4);
            }
            if (tid < KT) {
                CK[tid*2+0] = ck[((size_t)b*Kd + k0 + tid)*2 + 0];
                CK[tid*2+1] = ck[((size_t)b*Kd + k0 + tid)*2 + 1];
            }
        }
        __syncthreads();

        // ---- phase A: S = (Q Kt)*scale, D = masked distances ----
        {
            float s[4][4];
            #pragma unroll
            for (int i = 0; i < 4; i++)
                #pragma unroll
                for (int j = 0; j < 4; j++) s[i][j] = 0.f;

            #pragma unroll 4
            for (int f = 0; f < Fd; f += 4) {
                float4 a[4], bb[4];
                #pragma unroll
                for (int i = 0; i < 4; i++) a[i]  = *(const float4*)(Qs + (aq0+i)*LSTR + f);
                #pragma unroll
                for (int j = 0; j < 4; j++) bb[j] = *(const float4*)(Ks + (ak0+j)*LSTR + f);
                #pragma unroll
                for (int i = 0; i < 4; i++)
                    #pragma unroll
                    for (int j = 0; j < 4; j++) {
                        s[i][j] += a[i].x*bb[j].x;
                        s[i][j] += a[i].y*bb[j].y;
                        s[i][j] += a[i].z*bb[j].z;
                        s[i][j] += a[i].w*bb[j].w;
                    }
            }

            #pragma unroll
            for (int i = 0; i < 4; i++) {
                size_t mbase = ((size_t)b*Qd + q0 + aq0 + i)*(size_t)Kd + k0 + ak0;
                int4 a4 = *(const int4*)(am  + mbase);   // masks are int32 (0/1)
                int4 l4 = *(const int4*)(alm + mbase);
                int av[4] = {a4.x, a4.y, a4.z, a4.w};
                int lv[4] = {l4.x, l4.y, l4.z, l4.w};
                float cqx = CQ[(aq0+i)*2+0], cqy = CQ[(aq0+i)*2+1];
                #pragma unroll
                for (int j = 0; j < 4; j++) {
                    float dx = cqx - CK[(ak0+j)*2+0];
                    float dy = cqy - CK[(ak0+j)*2+1];
                    float dist = sqrtf(dx*dx + dy*dy) * dscale;
                    float dv = lv[j] ? 0.f : dist;          // alibi mask -> 0
                    dv = av[j] ? -1.f : dv;                  // attn mask encoded as sign
                    SE[(aq0+i)*SSTR + ak0 + j] = s[i][j] * sscale;
                    DD[(aq0+i)*SSTR + ak0 + j] = dv;
                }
            }
        }
        __syncthreads();

        // ---- phase A2: online softmax row update (4 threads / row) ----
        {
            int r   = tid >> 2;
            int sub = tid & 3;
            float mloc = -INFINITY;
            #pragma unroll
            for (int j = 0; j < 16; j++)
                mloc = fmaxf(mloc, SE[r*SSTR + sub*16 + j]);
            mloc = fmaxf(mloc, __shfl_xor_sync(0xffffffffu, mloc, 1));
            mloc = fmaxf(mloc, __shfl_xor_sync(0xffffffffu, mloc, 2));

            float mold = MR[r];
            float mnew = fmaxf(mold, mloc);

            float esum = 0.f;
            #pragma unroll
            for (int j = 0; j < 16; j++) {
                int idx = r*SSTR + sub*16 + j;
                float e = __expf(SE[idx] - mnew);   // l sums over ALL k (pre-mask softmax)
                esum += e;
                float dv = DD[idx];
                SE[idx] = (dv < 0.f) ? 0.f : e;      // attn-masked -> numerator excluded
                DD[idx] = fmaxf(dv, 0.f);            // restore masked distance
            }
            esum += __shfl_xor_sync(0xffffffffu, esum, 1);
            esum += __shfl_xor_sync(0xffffffffu, esum, 2);

            if (sub == 0) {
                float rsf = (mold == -INFINITY) ? 0.f : __expf(mold - mnew);
                MR[r] = mnew;
                LR[r] = LR[r]*rsf + esum;
                RS[r] = rsf;
            }
        }
        __syncthreads();

        // ---- phase B: acc1 += E @ V ; acc2 += D @ V ----
        {
            #pragma unroll
            for (int i = 0; i < 8; i++) {
                float rsf = RS[bq0 + i];
                #pragma unroll
                for (int c = 0; c < 4; c++) acc1[i][c] *= rsf;
            }
            #pragma unroll 4
            for (int kk = 0; kk < KT; kk++) {
                float4 v4 = *(const float4*)(Vs + kk*LSTR + bf0);
                #pragma unroll
                for (int i = 0; i < 8; i++) {
                    float e = SE[(bq0+i)*SSTR + kk];
                    float d = DD[(bq0+i)*SSTR + kk];
                    acc1[i][0] += e*v4.x; acc1[i][1] += e*v4.y;
                    acc1[i][2] += e*v4.z; acc1[i][3] += e*v4.w;
                    acc2[i][0] += d*v4.x; acc2[i][1] += d*v4.y;
                    acc2[i][2] += d*v4.z; acc2[i][3] += d*v4.w;
                }
            }
        }
        __syncthreads();
    }

    // ---- epilogue: O = acc1/l - acc2 ----
    #pragma unroll
    for (int i = 0; i < 8; i++) {
        float invl = 1.f / LR[bq0 + i];
        float4 o;
        o.x = acc1[i][0]*invl - acc2[i][0];
        o.y = acc1[i][1]*invl - acc2[i][1];
        o.z = acc1[i][2]*invl - acc2[i][2];
        o.w = acc1[i][3]*invl - acc2[i][3];
        *(float4*)(out + ((size_t)b*Qd + q0 + bq0 + i)*Fd + bf0) = o;
    }
}

extern "C" void kernel_launch(void* const* d_in, const int* in_sizes, int n_in,
                              void* d_out, int out_size) {
    const float* q   = (const float*)d_in[0];
    const float* k   = (const float*)d_in[1];
    const float* v   = (const float*)d_in[2];
    const float* cq  = (const float*)d_in[3];
    const float* ck  = (const float*)d_in[4];
    const int* am    = (const int*)d_in[5];
    const int* alm   = (const int*)d_in[6];
    const float* bs  = (const float*)d_in[7];
    const float* rm  = (const float*)d_in[8];
    float* out = (float*)d_out;

    cudaFuncSetAttribute(alibi_attn_kernel,
                         cudaFuncAttributeMaxDynamicSharedMemorySize, SMEM_BYTES);

    dim3 grid(Qd/QT, Bb);
    alibi_attn_kernel<<<grid, NT, SMEM_BYTES>>>(q, k, v, cq, ck, am, alm, bs, rm, out);
}